// round 1
// baseline (speedup 1.0000x reference)
#include <cuda_runtime.h>
#include <math.h>

#define BATCH 256
#define HID   1024
#define H3    3072
#define VOC   512
#define TT    256
#define FPD   2048

// ---------------- scratch (__device__ globals; no allocation allowed) ----------------
__device__ float g_h0[2][BATCH * HID];
__device__ float g_h1[2][BATCH * HID];
__device__ float g_G0[VOC * H3];          // relu(emb) @ W_ih0^T + b_ih0, per-token gate table
__device__ float g_gh1[BATCH * H3];       // h1_prev @ W_hh1^T + b_hh1
__device__ float g_Hbuf[(size_t)TT * BATCH * HID];  // all h1 states for deferred output GEMM

// ---------------- helpers ----------------
__device__ __forceinline__ unsigned f2tf(float f) {
    unsigned u;
    asm("cvt.rna.tf32.f32 %0, %1;" : "=r"(u) : "f"(f));
    return u;
}

__device__ __forceinline__ void mma8(float c[4], const unsigned a[4], const unsigned b[2]) {
    asm volatile(
        "mma.sync.aligned.m16n8k8.row.col.f32.tf32.tf32.f32 "
        "{%0,%1,%2,%3},{%4,%5,%6,%7},{%8,%9},{%0,%1,%2,%3};"
        : "+f"(c[0]), "+f"(c[1]), "+f"(c[2]), "+f"(c[3])
        : "r"(a[0]), "r"(a[1]), "r"(a[2]), "r"(a[3]), "r"(b[0]), "r"(b[1]));
}

__device__ __forceinline__ float sigm(float x) { return 1.0f / (1.0f + __expf(-x)); }

// ---------------- plain 64x64 GEMM core: C[m,n] = sum_k A[m,k]*W[n,k] ----------------
// 256 threads, 8 warps as 2(M) x 4(N); warp tile 32x16; BK=32.
__device__ __forceinline__ void gemm64x64(const float* A, int lda, const float* W, int ldw,
                                          int K, int m0, int n0, int reluA,
                                          unsigned* As, unsigned* Bs, float c[2][2][4]) {
    const int tid = threadIdx.x, lane = tid & 31, wid = tid >> 5;
    const int g = lane >> 2, t4 = lane & 3;
    const int warpM = wid >> 2, warpN = wid & 3;

    for (int kk = 0; kk < K; kk += 32) {
#pragma unroll
        for (int p = 0; p < 2; p++) {
            int r = p * 32 + (tid >> 3);
            int c4 = (tid & 7) * 4;
            float4 v = *(const float4*)(A + (size_t)(m0 + r) * lda + kk + c4);
            if (reluA) { v.x = fmaxf(v.x, 0.f); v.y = fmaxf(v.y, 0.f); v.z = fmaxf(v.z, 0.f); v.w = fmaxf(v.w, 0.f); }
            unsigned* d = As + r * 36 + c4;
            d[0] = f2tf(v.x); d[1] = f2tf(v.y); d[2] = f2tf(v.z); d[3] = f2tf(v.w);
            float4 w = *(const float4*)(W + (size_t)(n0 + r) * ldw + kk + c4);
            unsigned* e = Bs + r * 36 + c4;
            e[0] = f2tf(w.x); e[1] = f2tf(w.y); e[2] = f2tf(w.z); e[3] = f2tf(w.w);
        }
        __syncthreads();
#pragma unroll
        for (int ks = 0; ks < 4; ks++) {
            int kb = ks * 8;
            unsigned a[2][4], b[2][2];
#pragma unroll
            for (int mt = 0; mt < 2; mt++) {
                int row = warpM * 32 + mt * 16 + g;
                a[mt][0] = As[row * 36 + kb + t4];
                a[mt][1] = As[(row + 8) * 36 + kb + t4];
                a[mt][2] = As[row * 36 + kb + t4 + 4];
                a[mt][3] = As[(row + 8) * 36 + kb + t4 + 4];
            }
#pragma unroll
            for (int nt = 0; nt < 2; nt++) {
                int nr = warpN * 16 + nt * 8 + g;
                b[nt][0] = Bs[nr * 36 + kb + t4];
                b[nt][1] = Bs[nr * 36 + kb + t4 + 4];
            }
#pragma unroll
            for (int mt = 0; mt < 2; mt++)
#pragma unroll
                for (int nt = 0; nt < 2; nt++) mma8(c[mt][nt], a[mt], b[nt]);
        }
        __syncthreads();
    }
}

// ---------------- triple-gate 64x(3x32) GEMM core over K=HID ----------------
// Computes, for j in [jb, jb+32): acc[g3] = A[m,:] . W[g3*HID + j, :]  (g3 = r/z/n gate)
// 256 threads, 8 warps as 4(M) x 2(Nj); warp tile 16 x 16 per gate.
__device__ __forceinline__ void gemm_triple(const float* A, const float* W, int m0, int jb,
                                            unsigned* As, unsigned* Bs, float c[3][2][4]) {
    const int tid = threadIdx.x, lane = tid & 31, wid = tid >> 5;
    const int g = lane >> 2, t4 = lane & 3;
    const int warpM = wid & 3, warpN = wid >> 2;

    for (int kk = 0; kk < HID; kk += 32) {
#pragma unroll
        for (int p = 0; p < 2; p++) {
            int r = p * 32 + (tid >> 3);
            int c4 = (tid & 7) * 4;
            float4 v = *(const float4*)(A + (size_t)(m0 + r) * HID + kk + c4);
            unsigned* d = As + r * 36 + c4;
            d[0] = f2tf(v.x); d[1] = f2tf(v.y); d[2] = f2tf(v.z); d[3] = f2tf(v.w);
        }
        {
            int r = tid >> 3;
            int c4 = (tid & 7) * 4;
#pragma unroll
            for (int g3 = 0; g3 < 3; g3++) {
                float4 w = *(const float4*)(W + (size_t)(g3 * HID + jb + r) * HID + kk + c4);
                unsigned* e = Bs + g3 * 1152 + r * 36 + c4;
                e[0] = f2tf(w.x); e[1] = f2tf(w.y); e[2] = f2tf(w.z); e[3] = f2tf(w.w);
            }
        }
        __syncthreads();
#pragma unroll
        for (int ks = 0; ks < 4; ks++) {
            int kb = ks * 8;
            unsigned a[4];
            int row = warpM * 16 + g;
            a[0] = As[row * 36 + kb + t4];
            a[1] = As[(row + 8) * 36 + kb + t4];
            a[2] = As[row * 36 + kb + t4 + 4];
            a[3] = As[(row + 8) * 36 + kb + t4 + 4];
#pragma unroll
            for (int g3 = 0; g3 < 3; g3++) {
#pragma unroll
                for (int nt = 0; nt < 2; nt++) {
                    unsigned b[2];
                    int nr = warpN * 16 + nt * 8 + g;
                    b[0] = Bs[g3 * 1152 + nr * 36 + kb + t4];
                    b[1] = Bs[g3 * 1152 + nr * 36 + kb + t4 + 4];
                    mma8(c[g3][nt], a, b);
                }
            }
        }
        __syncthreads();
    }
}

// ---------------- kernels ----------------

// h0 = relu(fingerprints @ Wc^T + bc), replicated into both layer states (buffer 0)
__global__ __launch_bounds__(256) void k_init_h0(const float* fp, const float* Wc, const float* bc) {
    __shared__ unsigned As[64 * 36], Bs[64 * 36];
    float c[2][2][4] = {};
    int n0 = blockIdx.x * 64, m0 = blockIdx.y * 64;
    gemm64x64(fp, FPD, Wc, FPD, FPD, m0, n0, 0, As, Bs, c);
    const int tid = threadIdx.x, lane = tid & 31, wid = tid >> 5;
    const int g = lane >> 2, t4 = lane & 3;
    const int warpM = wid >> 2, warpN = wid & 3;
#pragma unroll
    for (int mt = 0; mt < 2; mt++)
#pragma unroll
        for (int nt = 0; nt < 2; nt++)
#pragma unroll
            for (int ci = 0; ci < 4; ci++) {
                int m = m0 + warpM * 32 + mt * 16 + g + ((ci & 2) ? 8 : 0);
                int n = n0 + warpN * 16 + nt * 8 + t4 * 2 + (ci & 1);
                float v = fmaxf(c[mt][nt][ci] + bc[n], 0.f);
                g_h0[0][m * HID + n] = v;
                g_h1[0][m * HID + n] = v;
            }
}

// G0[v, :] = relu(emb[v,:]) @ W_ih0^T + b_ih0
__global__ __launch_bounds__(256) void k_init_G0(const float* emb, const float* Wih, const float* bih) {
    __shared__ unsigned As[64 * 36], Bs[64 * 36];
    float c[2][2][4] = {};
    int n0 = blockIdx.x * 64, m0 = blockIdx.y * 64;
    gemm64x64(emb, HID, Wih, HID, HID, m0, n0, 1, As, Bs, c);
    const int tid = threadIdx.x, lane = tid & 31, wid = tid >> 5;
    const int g = lane >> 2, t4 = lane & 3;
    const int warpM = wid >> 2, warpN = wid & 3;
#pragma unroll
    for (int mt = 0; mt < 2; mt++)
#pragma unroll
        for (int nt = 0; nt < 2; nt++)
#pragma unroll
            for (int ci = 0; ci < 4; ci++) {
                int m = m0 + warpM * 32 + mt * 16 + g + ((ci & 2) ? 8 : 0);
                int n = n0 + warpN * 16 + nt * 8 + t4 * 2 + (ci & 1);
                g_G0[m * H3 + n] = c[mt][nt][ci] + bih[n];
            }
}

// Step kernel A:
//  z==0: gh0 = h0_prev @ W_hh0^T + b_hh0 ; fuse layer-0 gates with G0[token] -> h0_new
//  z==1: gh1 = h1_prev @ W_hh1^T + b_hh1 -> g_gh1 (plain store)
__global__ __launch_bounds__(256) void k_stepA(int t, const int* tgt, const float* Whh, const float* bhh) {
    __shared__ unsigned As[64 * 36], Bs[3 * 32 * 36];
    const int layer = blockIdx.z;
    const float* h0_in = g_h0[t & 1];
    const float* h1_in = g_h1[t & 1];
    float* h0_out = g_h0[(t + 1) & 1];
    const float* A = layer ? h1_in : h0_in;
    const float* W = Whh + (size_t)layer * H3 * HID;
    const float* bh = bhh + layer * H3;
    int m0 = blockIdx.y * 64, jb = blockIdx.x * 32;
    float c[3][2][4] = {};
    gemm_triple(A, W, m0, jb, As, Bs, c);

    const int tid = threadIdx.x, lane = tid & 31, wid = tid >> 5;
    const int g = lane >> 2, t4 = lane & 3;
    const int warpM = wid & 3, warpN = wid >> 2;
#pragma unroll
    for (int nt = 0; nt < 2; nt++)
#pragma unroll
        for (int ci = 0; ci < 4; ci++) {
            int m = m0 + warpM * 16 + g + ((ci & 2) ? 8 : 0);
            int j = jb + warpN * 16 + nt * 8 + t4 * 2 + (ci & 1);
            float ghr = c[0][nt][ci] + bh[j];
            float ghz = c[1][nt][ci] + bh[HID + j];
            float ghn = c[2][nt][ci] + bh[2 * HID + j];
            if (layer == 0) {
                int tok = (t == 0) ? 0 : tgt[m * TT + t - 1];
                const float* grow = g_G0 + (size_t)tok * H3;
                float r = sigm(grow[j] + ghr);
                float z = sigm(grow[HID + j] + ghz);
                float n = tanhf(grow[2 * HID + j] + r * ghn);
                float hp = h0_in[m * HID + j];
                h0_out[m * HID + j] = (1.0f - z) * n + z * hp;
            } else {
                g_gh1[m * H3 + j] = ghr;
                g_gh1[m * H3 + HID + j] = ghz;
                g_gh1[m * H3 + 2 * HID + j] = ghn;
            }
        }
}

// Step kernel B: gi1 = h0_new @ W_ih1^T + b_ih1 ; fuse layer-1 gates with g_gh1 -> h1_new, store to Hbuf
__global__ __launch_bounds__(256) void k_stepB(int t, const float* Wih, const float* bih) {
    __shared__ unsigned As[64 * 36], Bs[3 * 32 * 36];
    const float* h0n = g_h0[(t + 1) & 1];
    const float* h1_in = g_h1[t & 1];
    float* h1_out = g_h1[(t + 1) & 1];
    const float* W = Wih + (size_t)H3 * HID;  // layer 1
    const float* bi = bih + H3;
    int m0 = blockIdx.y * 64, jb = blockIdx.x * 32;
    float c[3][2][4] = {};
    gemm_triple(h0n, W, m0, jb, As, Bs, c);

    const int tid = threadIdx.x, lane = tid & 31, wid = tid >> 5;
    const int g = lane >> 2, t4 = lane & 3;
    const int warpM = wid & 3, warpN = wid >> 2;
#pragma unroll
    for (int nt = 0; nt < 2; nt++)
#pragma unroll
        for (int ci = 0; ci < 4; ci++) {
            int m = m0 + warpM * 16 + g + ((ci & 2) ? 8 : 0);
            int j = jb + warpN * 16 + nt * 8 + t4 * 2 + (ci & 1);
            float gir = c[0][nt][ci] + bi[j];
            float giz = c[1][nt][ci] + bi[HID + j];
            float gin = c[2][nt][ci] + bi[2 * HID + j];
            float r = sigm(gir + g_gh1[m * H3 + j]);
            float z = sigm(giz + g_gh1[m * H3 + HID + j]);
            float n = tanhf(gin + r * g_gh1[m * H3 + 2 * HID + j]);
            float hp = h1_in[m * HID + j];
            float hn = (1.0f - z) * n + z * hp;
            h1_out[m * HID + j] = hn;
            g_Hbuf[(size_t)t * BATCH * HID + (size_t)m * HID + j] = hn;
        }
}

// logits = Hbuf @ Wo^T + bo, written to out at [b, t, v]  (Hbuf rows are t*B+b)
__global__ __launch_bounds__(256) void k_logits(const float* Wo, const float* bo, float* out) {
    __shared__ unsigned As[64 * 36], Bs[64 * 36];
    float c[2][2][4] = {};
    int n0 = blockIdx.x * 64, m0 = blockIdx.y * 64;
    gemm64x64(g_Hbuf, HID, Wo, HID, HID, m0, n0, 0, As, Bs, c);
    const int tid = threadIdx.x, lane = tid & 31, wid = tid >> 5;
    const int g = lane >> 2, t4 = lane & 3;
    const int warpM = wid >> 2, warpN = wid & 3;
#pragma unroll
    for (int mt = 0; mt < 2; mt++)
#pragma unroll
        for (int nt = 0; nt < 2; nt++)
#pragma unroll
            for (int ci = 0; ci < 4; ci++) {
                int m = m0 + warpM * 32 + mt * 16 + g + ((ci & 2) ? 8 : 0);
                int n = n0 + warpN * 16 + nt * 8 + t4 * 2 + (ci & 1);
                int bb = m & (BATCH - 1);
                int tt = m >> 8;
                out[((size_t)bb * TT + tt) * VOC + n] = c[mt][nt][ci] + bo[n];
            }
}

// in-place log_softmax over the last dim (V=512), one block (128 thr) per row
__global__ __launch_bounds__(128) void k_lsm(float* out) {
    float* p = out + (size_t)blockIdx.x * VOC;
    const int tid = threadIdx.x, lane = tid & 31, wid = tid >> 5;
    __shared__ float smx[4], ssm[4];
    float v[4];
#pragma unroll
    for (int i = 0; i < 4; i++) v[i] = p[tid + 128 * i];
    float mx = fmaxf(fmaxf(v[0], v[1]), fmaxf(v[2], v[3]));
#pragma unroll
    for (int o = 16; o; o >>= 1) mx = fmaxf(mx, __shfl_xor_sync(0xffffffffu, mx, o));
    if (lane == 0) smx[wid] = mx;
    __syncthreads();
    mx = fmaxf(fmaxf(smx[0], smx[1]), fmaxf(smx[2], smx[3]));
    float s = 0.f;
#pragma unroll
    for (int i = 0; i < 4; i++) s += __expf(v[i] - mx);
#pragma unroll
    for (int o = 16; o; o >>= 1) s += __shfl_xor_sync(0xffffffffu, s, o);
    if (lane == 0) ssm[wid] = s;
    __syncthreads();
    s = ssm[0] + ssm[1] + ssm[2] + ssm[3];
    float lse = mx + logf(s);
#pragma unroll
    for (int i = 0; i < 4; i++) p[tid + 128 * i] = v[i] - lse;
}

// copy final hidden states [L,B,H] to the tail of out (after 256 steps, state is in buffer 0)
__global__ __launch_bounds__(512) void k_hfinal(float* outh) {
    int i = blockIdx.x * blockDim.x + threadIdx.x;
    if (i < BATCH * HID) outh[i] = g_h0[0][i];
    else outh[i] = g_h1[0][i - BATCH * HID];
}

// ---------------- launch ----------------
extern "C" void kernel_launch(void* const* d_in, const int* in_sizes, int n_in,
                              void* d_out, int out_size) {
    (void)in_sizes; (void)n_in; (void)out_size;
    const float* fp   = (const float*)d_in[1];
    const int*   tgt  = (const int*)d_in[2];
    const float* emb  = (const float*)d_in[3];
    const float* Wc   = (const float*)d_in[4];
    const float* bc   = (const float*)d_in[5];
    const float* W_ih = (const float*)d_in[6];
    const float* W_hh = (const float*)d_in[7];
    const float* b_ih = (const float*)d_in[8];
    const float* b_hh = (const float*)d_in[9];
    const float* Wo   = (const float*)d_in[10];
    const float* bo   = (const float*)d_in[11];
    float* out = (float*)d_out;

    k_init_h0<<<dim3(16, 4), 256>>>(fp, Wc, bc);
    k_init_G0<<<dim3(48, 8), 256>>>(emb, W_ih, b_ih);
    for (int t = 0; t < TT; t++) {
        k_stepA<<<dim3(32, 4, 2), 256>>>(t, tgt, W_hh, b_hh);
        k_stepB<<<dim3(32, 4), 256>>>(t, W_ih, b_ih);
    }
    k_logits<<<dim3(8, 1024), 256>>>(Wo, bo, out);
    k_lsm<<<65536, 128>>>(out);
    k_hfinal<<<1024, 512>>>(out + (size_t)BATCH * TT * VOC);
}